// round 8
// baseline (speedup 1.0000x reference)
#include <cuda_runtime.h>
#include <cstdint>

// NHConv via tf32 mma.sync m16n8k8.
// out[b,n,o] = sum_{k,f} x[b, adjc[n,k], f] * W[k,f,o] + bias[o]
// Warp tile: 48 M-rows x 64 N-cols, K' = 576. 3-stage cp.async quarter-k
// pipeline (issue 2 ahead), all LDSM/cp.async addresses hoisted to
// base + literal. W (tf32-RN, [k][o][f]) resident in smem. Persistent grid.
// A unrounded (mma truncates); W pre-rounded RN.

#define KNBR   9
#define FDIM   64
#define MW     48
#define WARPS  8
#define NTHREADS 256

#define W_BYTES (KNBR * FDIM * FDIM * 4)      // 147456
#define QSTG   3072                            // 48 rows * 64 B
#define NSTAGE 3
#define ABUF   (NSTAGE * QSTG)                 // 9216 per warp
#define SMEM_TOTAL (W_BYTES + WARPS * ABUF)    // 221184

__device__ float g_Wt[KNBR * FDIM * FDIM];     // [k][o][f], tf32-RN

__global__ void prep_W(const float* __restrict__ W) {
    int idx = blockIdx.x * 256 + threadIdx.x;
    if (idx >= KNBR * FDIM * FDIM) return;
    int k = idx >> 12, rem = idx & 4095, o = rem >> 6, f = rem & 63;
    float v = W[(k << 12) + (f << 6) + o];
    uint32_t t;
    asm("cvt.rna.tf32.f32 %0, %1;" : "=r"(t) : "f"(v));
    g_Wt[idx] = __uint_as_float(t);
}

static __device__ __forceinline__ uint32_t smem_u32(const void* p) {
    uint32_t a;
    asm("{ .reg .u64 t; cvta.to.shared.u64 t, %1; cvt.u32.u64 %0, t; }" : "=r"(a) : "l"(p));
    return a;
}

#define LDSM4(r, addr)                                                          \
    asm volatile("ldmatrix.sync.aligned.m8n8.x4.shared.b16 {%0,%1,%2,%3}, [%4];" \
        : "=r"((r)[0]), "=r"((r)[1]), "=r"((r)[2]), "=r"((r)[3]) : "r"(addr))

static __device__ __forceinline__ void mma_tf32(float* c, uint32_t a0, uint32_t a1,
                                                uint32_t a2, uint32_t a3,
                                                uint32_t b0, uint32_t b1) {
    asm volatile(
        "mma.sync.aligned.m16n8k8.row.col.f32.tf32.tf32.f32 "
        "{%0,%1,%2,%3}, {%4,%5,%6,%7}, {%8,%9}, {%0,%1,%2,%3};"
        : "+f"(c[0]), "+f"(c[1]), "+f"(c[2]), "+f"(c[3])
        : "r"(a0), "r"(a1), "r"(a2), "r"(a3), "r"(b0), "r"(b1));
}

// issue quarter QL of current srcp into stage S (literal S, QL)
#define ISSUEQ(S, QL) do {                                                       \
    _Pragma("unroll")                                                            \
    for (int _i = 0; _i < 6; _i++) {                                             \
        uint32_t _d = dstb + _i * 512 + (S) * QSTG;                              \
        asm volatile("cp.async.cg.shared.global [%0], [%1], 16;"                 \
            :: "r"(_d), "l"(srcp[_i] + (QL) * 64) : "memory");                   \
    }                                                                            \
    asm volatile("cp.async.commit_group;" ::: "memory");                         \
} while (0)

#define WAITN(N) do {                                                            \
    asm volatile("cp.async.wait_group %0;" :: "n"(N) : "memory");                \
    __syncwarp();                                                                \
} while (0)

#define LOADIDX(J) do {                                                          \
    _Pragma("unroll") for (int _i = 0; _i < 6; _i++) idxn[_i] = apk[_i][(J)];    \
} while (0)

#define NEWSRC() do {                                                            \
    _Pragma("unroll") for (int _i = 0; _i < 6; _i++)                             \
        srcp[_i] = xbc + (size_t)(uint32_t)idxn[_i] * 256 + gg16;                \
} while (0)

// compute 2 k-steps of quarter Q from stage S against W tile at WK (S,Q literal)
#define COMPUTE_Q(S, WK, Q) do {                                                 \
    _Pragma("unroll")                                                            \
    for (int _s = 0; _s < 2; _s++) {                                             \
        uint32_t rA0[4], rA1[4], rA2[4];                                         \
        LDSM4(rA0, aA0[_s] + (S) * QSTG);                                        \
        LDSM4(rA1, aA0[_s] + (S) * QSTG + 1024);                                 \
        LDSM4(rA2, aA0[_s] + (S) * QSTG + 2048);                                 \
        const int _sg = (Q) * 2 + _s;                                            \
        _Pragma("unroll")                                                        \
        for (int _pq = 0; _pq < 4; _pq++) {                                      \
            uint32_t rB[4];                                                      \
            LDSM4(rB, (WK) + wkoff[_sg] + _pq * 4096);                           \
            mma_tf32(acc[0][2*_pq],   rA0[0], rA0[2], rA0[1], rA0[3], rB[0], rB[1]); \
            mma_tf32(acc[1][2*_pq],   rA1[0], rA1[2], rA1[1], rA1[3], rB[0], rB[1]); \
            mma_tf32(acc[2][2*_pq],   rA2[0], rA2[2], rA2[1], rA2[3], rB[0], rB[1]); \
            mma_tf32(acc[0][2*_pq+1], rA0[0], rA0[2], rA0[1], rA0[3], rB[2], rB[3]); \
            mma_tf32(acc[1][2*_pq+1], rA1[0], rA1[2], rA1[1], rA1[3], rB[2], rB[3]); \
            mma_tf32(acc[2][2*_pq+1], rA2[0], rA2[2], rA2[1], rA2[3], rB[2], rB[3]); \
        }                                                                        \
    }                                                                            \
} while (0)

// stage of quarter q of k with k%3 == J (J, q literal)
#define S_(J, Q) (((J) + (Q)) % 3)

// steady-state body for k with k%3 == J (issues 2 quarters ahead)
#define K3BODY(J, WK) do {                                                       \
    LOADIDX((J) + 1);                                                            \
    ISSUEQ(S_(J, 2), 2); WAITN(2); COMPUTE_Q(S_(J, 0), WK, 0);                   \
    ISSUEQ(S_(J, 3), 3); WAITN(2); COMPUTE_Q(S_(J, 1), WK, 1);                   \
    NEWSRC();                                                                    \
    ISSUEQ(S_((J) + 1, 0), 0); WAITN(2); COMPUTE_Q(S_(J, 2), WK, 2);             \
    ISSUEQ(S_((J) + 1, 1), 1); WAITN(2); COMPUTE_Q(S_(J, 3), WK, 3);             \
} while (0)

// tail body: k = 8 (k%3 == 2), no further issues
#define K8TAIL(WK) do {                                                          \
    ISSUEQ(S_(2, 2), 2); WAITN(2); COMPUTE_Q(S_(2, 0), WK, 0);                   \
    ISSUEQ(S_(2, 3), 3); WAITN(2); COMPUTE_Q(S_(2, 1), WK, 1);                   \
    WAITN(1);            COMPUTE_Q(S_(2, 2), WK, 2);                             \
    WAITN(0);            COMPUTE_Q(S_(2, 3), WK, 3);                             \
} while (0)

__global__ __launch_bounds__(NTHREADS, 1)
void nhconv_p3(const float* __restrict__ x,
               const int* __restrict__ adjc,
               const float* __restrict__ bias,
               float* __restrict__ out,
               int Nn, int nwt)
{
    extern __shared__ char smem[];
    const uint32_t sbase = smem_u32(smem);
    const int tid  = threadIdx.x;
    const int lane = tid & 31;
    const int w    = tid >> 5;

    // stage all 9 W tiles, swizzled: byte = k*16384 + o*256 + ((c ^ (o&7))<<4)
    for (int q = tid; q < KNBR * FDIM * 16; q += NTHREADS) {
        int k = q >> 10, o = (q >> 4) & 63, c = q & 15;
        float4 v = reinterpret_cast<const float4*>(g_Wt)[q];
        *reinterpret_cast<float4*>(smem + k * 16384 + o * 256 + ((c ^ (o & 7)) << 4)) = v;
    }
    __syncthreads();

    const uint32_t wB   = sbase;
    const uint32_t wbuf = sbase + W_BYTES + w * ABUF;

    // gather roles: lane covers rows gr+8i (i=0..5), f-chunk gg (16B)
    const int gr = lane >> 2;
    const int gg = lane & 3;
    const uint32_t gsw  = (uint32_t)(((gg + (gr >> 1)) & 3) << 4);
    const uint32_t dstb = wbuf + (uint32_t)(gr * 64) + gsw;
    const size_t   gg16 = (size_t)(gg * 16);

    // ldmatrix roles
    const int lr      = lane & 7;
    const int grp     = lane >> 3;
    const int halfsel = grp & 1;
    const int rhi     = (grp >> 1) << 3;
    uint32_t aA0[2];
#pragma unroll
    for (int s = 0; s < 2; s++)
        aA0[s] = wbuf + (uint32_t)((rhi + lr) * 64)
               + (uint32_t)((((2 * s + halfsel) + (lr >> 1)) & 3) << 4);
    uint32_t wkoff[8];
#pragma unroll
    for (int s = 0; s < 8; s++)
        wkoff[s] = (uint32_t)((rhi + lr) * 256)
                 + (uint32_t)(((2 * s + halfsel) ^ lr) << 4);

    // bias fragment
    const int tig = lane & 3;
    float2 bj[8];
#pragma unroll
    for (int j = 0; j < 8; j++)
        bj[j] = *reinterpret_cast<const float2*>(bias + 8 * j + 2 * tig);

    float acc[3][8][4];
#pragma unroll
    for (int t = 0; t < 3; t++)
#pragma unroll
        for (int j = 0; j < 8; j++)
#pragma unroll
            for (int r = 0; r < 4; r++) acc[t][j][r] = 0.0f;

    const int gw      = blockIdx.x * WARPS + w;
    const int wstride = gridDim.x * WARPS;

    for (int wt = gw; wt < nwt; wt += wstride) {
        const long long m0 = (long long)wt * MW;
        const int b  = (int)(m0 / Nn);
        const int n0 = (int)(m0 - (long long)b * Nn);
        const char* xbc = reinterpret_cast<const char*>(x + (size_t)b * Nn * FDIM);
        const int* arow = adjc + (size_t)n0 * KNBR;

        const int* apk[6];
        int idxn[6];
        const char* srcp[6];
#pragma unroll
        for (int i = 0; i < 6; i++) apk[i] = arow + (gr + 8 * i) * KNBR;

        // prologue: k=0 src, issue q0,q1 (stages 0,1)
        LOADIDX(0);
        NEWSRC();
        ISSUEQ(0, 0);
        ISSUEQ(1, 1);

#pragma unroll 1
        for (int kb = 0; kb < 2; kb++) {
            const uint32_t wkb = wB + (uint32_t)kb * 49152u;
            K3BODY(0, wkb);
            K3BODY(1, wkb + 16384u);
            K3BODY(2, wkb + 32768u);
#pragma unroll
            for (int i = 0; i < 6; i++) apk[i] += 3;
        }
        {
            const uint32_t wkb = wB + 98304u;
            K3BODY(0, wkb);            // k=6
            K3BODY(1, wkb + 16384u);   // k=7 (issues q0,q1 of k=8)
            K8TAIL(wkb + 32768u);      // k=8
        }

        // epilogue: bias + store, zero acc
        const int g = lane >> 2;
#pragma unroll
        for (int t = 0; t < 3; t++) {
            float* r0 = out + (size_t)(m0 + t * 16 + g) * FDIM;
            float* r1 = r0 + 8 * FDIM;
#pragma unroll
            for (int j = 0; j < 8; j++) {
                int col = 8 * j + 2 * tig;
                float2 o0 = { acc[t][j][0] + bj[j].x, acc[t][j][1] + bj[j].y };
                float2 o1 = { acc[t][j][2] + bj[j].x, acc[t][j][3] + bj[j].y };
                *reinterpret_cast<float2*>(r0 + col) = o0;
                *reinterpret_cast<float2*>(r1 + col) = o1;
                acc[t][j][0] = 0.f; acc[t][j][1] = 0.f;
                acc[t][j][2] = 0.f; acc[t][j][3] = 0.f;
            }
        }
    }
}

extern "C" void kernel_launch(void* const* d_in, const int* in_sizes, int n_in,
                              void* d_out, int out_size)
{
    const float* x    = (const float*)d_in[0];   // (B, N, 64) fp32
    const int*   adjc = (const int*)d_in[1];     // (N, 9) int32
    const float* W    = (const float*)d_in[2];   // (9, 64, 64) fp32
    const float* bias = (const float*)d_in[3];   // (64,) fp32
    float*       out  = (float*)d_out;

    const int Nn = in_sizes[1] / KNBR;
    const long long M = (long long)out_size / FDIM;
    const int nwt = (int)(M / MW);               // 8192 warp-tiles

    cudaFuncSetAttribute(nhconv_p3, cudaFuncAttributeMaxDynamicSharedMemorySize, SMEM_TOTAL);

    int nsm = 148;
    cudaDeviceGetAttribute(&nsm, cudaDevAttrMultiProcessorCount, 0);

    prep_W<<<(KNBR * FDIM * FDIM + 255) / 256, 256>>>(W);
    nhconv_p3<<<nsm, NTHREADS, SMEM_TOTAL>>>(x, adjc, bias, out, Nn, nwt);
}

// round 9
// speedup vs baseline: 1.1191x; 1.1191x over previous
#include <cuda_runtime.h>
#include <cstdint>

// NHConv via tf32 mma.sync m16n8k8.
// out[b,n,o] = sum_{k,f} x[b, adjc[n,k], f] * W[k,f,o] + bias[o]
// Warp tile: 32 M-rows x 64 N-cols, K' = 576. 512-thread CTA (16 warps,
// 4/SMSP) for occupancy; 2-stage cp.async quarter-k pipeline; atomic
// work-stealing over 12288 warp-tiles. W (tf32-RN, [k][o][f]) resident in
// smem. A unrounded (mma truncates); W pre-rounded RN.

#define KNBR   9
#define FDIM   64
#define MW     32
#define WARPS  16
#define NTHREADS 512

#define W_BYTES (KNBR * FDIM * FDIM * 4)        // 147456
#define QSTG   2048                              // 32 rows * 64 B
#define ABUF   (2 * QSTG)                        // 4096 per warp
#define OFF_BIAS (W_BYTES + WARPS * ABUF)        // 212992
#define SMEM_TOTAL (OFF_BIAS + 256)              // 213248

__device__ float g_Wt[KNBR * FDIM * FDIM];       // [k][o][f], tf32-RN
__device__ unsigned g_ctr;

__global__ void prep_W(const float* __restrict__ W) {
    int idx = blockIdx.x * 256 + threadIdx.x;
    if (idx == 0) g_ctr = 0;                     // reset work-steal counter (per replay)
    if (idx >= KNBR * FDIM * FDIM) return;
    int k = idx >> 12, rem = idx & 4095, o = rem >> 6, f = rem & 63;
    float v = W[(k << 12) + (f << 6) + o];
    uint32_t t;
    asm("cvt.rna.tf32.f32 %0, %1;" : "=r"(t) : "f"(v));
    g_Wt[idx] = __uint_as_float(t);
}

static __device__ __forceinline__ uint32_t smem_u32(const void* p) {
    uint32_t a;
    asm("{ .reg .u64 t; cvta.to.shared.u64 t, %1; cvt.u32.u64 %0, t; }" : "=r"(a) : "l"(p));
    return a;
}

#define LDSM4(r, addr)                                                          \
    asm volatile("ldmatrix.sync.aligned.m8n8.x4.shared.b16 {%0,%1,%2,%3}, [%4];" \
        : "=r"((r)[0]), "=r"((r)[1]), "=r"((r)[2]), "=r"((r)[3]) : "r"(addr))

static __device__ __forceinline__ void mma_tf32(float* c, uint32_t a0, uint32_t a1,
                                                uint32_t a2, uint32_t a3,
                                                uint32_t b0, uint32_t b1) {
    asm volatile(
        "mma.sync.aligned.m16n8k8.row.col.f32.tf32.tf32.f32 "
        "{%0,%1,%2,%3}, {%4,%5,%6,%7}, {%8,%9}, {%0,%1,%2,%3};"
        : "+f"(c[0]), "+f"(c[1]), "+f"(c[2]), "+f"(c[3])
        : "r"(a0), "r"(a1), "r"(a2), "r"(a3), "r"(b0), "r"(b1));
}

// issue one quarter-k gather (16 f-elems, 32 rows) into stage at DSTB
#define ISSUE_Q(DSTB, QQ) do {                                                   \
    _Pragma("unroll")                                                            \
    for (int _i = 0; _i < 4; _i++) {                                             \
        uint32_t _d = (DSTB) + _i * 512;                                         \
        asm volatile("cp.async.cg.shared.global [%0], [%1], 16;"                 \
            :: "r"(_d), "l"(srcp[_i] + (QQ) * 64) : "memory");                   \
    }                                                                            \
    asm volatile("cp.async.commit_group;" ::: "memory");                         \
} while (0)

#define WAITG(N) do {                                                            \
    asm volatile("cp.async.wait_group %0;" :: "n"(N) : "memory");                \
    __syncwarp();                                                                \
} while (0)

#define NEWSRC(K) do {                                                           \
    _Pragma("unroll")                                                            \
    for (int _i = 0; _i < 4; _i++)                                               \
        srcp[_i] = xbc + (size_t)(uint32_t)adjc[abase + _i * 72 + (K)] * 256     \
                   + gg16;                                                       \
} while (0)

// compute 2 k-steps of quarter Q from STAGE against W tile at WK
#define COMPUTE_Q(STAGE, WK, Q) do {                                             \
    _Pragma("unroll")                                                            \
    for (int _s = 0; _s < 2; _s++) {                                             \
        uint32_t rA0[4], rA1[4];                                                 \
        LDSM4(rA0, (STAGE) + rowA + gAq[_s]);                                    \
        LDSM4(rA1, (STAGE) + 1024 + rowA + gAq[_s]);                             \
        const int _sg = (Q) * 2 + _s;                                            \
        _Pragma("unroll")                                                        \
        for (int _pq = 0; _pq < 4; _pq++) {                                      \
            uint32_t rB[4];                                                      \
            LDSM4(rB, (WK) + wkoff[_sg] + _pq * 4096);                           \
            mma_tf32(acc[0][2*_pq],   rA0[0], rA0[2], rA0[1], rA0[3], rB[0], rB[1]); \
            mma_tf32(acc[1][2*_pq],   rA1[0], rA1[2], rA1[1], rA1[3], rB[0], rB[1]); \
            mma_tf32(acc[0][2*_pq+1], rA0[0], rA0[2], rA0[1], rA0[3], rB[2], rB[3]); \
            mma_tf32(acc[1][2*_pq+1], rA1[0], rA1[2], rA1[1], rA1[3], rB[2], rB[3]); \
        }                                                                        \
    }                                                                            \
} while (0)

__global__ __launch_bounds__(NTHREADS, 1)
void nhconv_ws(const float* __restrict__ x,
               const int* __restrict__ adjc,
               const float* __restrict__ bias,
               float* __restrict__ out,
               int Nn, int nwt)
{
    extern __shared__ char smem[];
    const uint32_t sbase = smem_u32(smem);
    const int tid  = threadIdx.x;
    const int lane = tid & 31;
    const int w    = tid >> 5;

    // stage all 9 W tiles, swizzled: byte = k*16384 + o*256 + ((c ^ (o&7))<<4)
    for (int q = tid; q < KNBR * FDIM * 16; q += NTHREADS) {
        int k = q >> 10, o = (q >> 4) & 63, c = q & 15;
        float4 v = reinterpret_cast<const float4*>(g_Wt)[q];
        *reinterpret_cast<float4*>(smem + k * 16384 + o * 256 + ((c ^ (o & 7)) << 4)) = v;
    }
    if (tid < 16)
        reinterpret_cast<float4*>(smem + OFF_BIAS)[tid] =
            reinterpret_cast<const float4*>(bias)[tid];
    __syncthreads();

    const uint32_t wB   = sbase;
    const uint32_t wbuf = sbase + W_BYTES + w * ABUF;  // stage0; stage1 = +QSTG

    // gather roles: lane covers rows gr+8i (i=0..3), f-chunk gg (16B)
    const int gr = lane >> 2;
    const int gg = lane & 3;
    const uint32_t gsw  = (uint32_t)(((gg + (gr >> 1)) & 3) << 4);
    const uint32_t dst0 = wbuf + (uint32_t)(gr * 64) + gsw;
    const size_t   gg16 = (size_t)(gg * 16);

    // ldmatrix roles
    const int lr      = lane & 7;
    const int grp     = lane >> 3;
    const int halfsel = grp & 1;
    const int rhi     = (grp >> 1) << 3;
    const uint32_t rowA = (uint32_t)((rhi + lr) * 64);
    uint32_t gAq[2], wkoff[8];
#pragma unroll
    for (int s = 0; s < 2; s++)
        gAq[s] = (uint32_t)((((2 * s + halfsel) + (lr >> 1)) & 3) << 4);
#pragma unroll
    for (int s = 0; s < 8; s++)
        wkoff[s] = (uint32_t)((rhi + lr) * 256)
                 + (uint32_t)(((2 * s + halfsel) ^ lr) << 4);

    const int tig = lane & 3;

    float acc[2][8][4];
#pragma unroll
    for (int t = 0; t < 2; t++)
#pragma unroll
        for (int j = 0; j < 8; j++)
#pragma unroll
            for (int r = 0; r < 4; r++) acc[t][j][r] = 0.0f;

    for (;;) {
        // work stealing: one tile per warp iteration
        unsigned wt;
        if (lane == 0) wt = atomicAdd(&g_ctr, 1u);
        wt = __shfl_sync(0xffffffffu, wt, 0);
        if (wt >= (unsigned)nwt) break;

        const long long m0 = (long long)wt * MW;
        const int b  = (int)(m0 / Nn);
        const int n0 = (int)(m0 - (long long)b * Nn);
        const char* xbc = reinterpret_cast<const char*>(x + (size_t)b * Nn * FDIM);
        const int abase = (n0 + gr) * KNBR;

        const char* srcp[4];
        NEWSRC(0);
        ISSUE_Q(dst0, 0);                        // q0 -> buf0

#pragma unroll 1
        for (int k = 0; k < KNBR; k++) {
            const uint32_t wk = wB + ((uint32_t)k << 14);

            ISSUE_Q(dst0 + QSTG, 1);             // q1 -> buf1
            WAITG(1);
            COMPUTE_Q(wbuf, wk, 0);

            ISSUE_Q(dst0, 2);                    // q2 -> buf0
            WAITG(1);
            COMPUTE_Q(wbuf + QSTG, wk, 1);

            ISSUE_Q(dst0 + QSTG, 3);             // q3 -> buf1
            WAITG(1);
            COMPUTE_Q(wbuf, wk, 2);

            if (k < KNBR - 1) {
                NEWSRC(k + 1);
                ISSUE_Q(dst0, 0);                // next k's q0 -> buf0
                WAITG(1);
            } else {
                WAITG(0);
            }
            COMPUTE_Q(wbuf + QSTG, wk, 3);
        }

        // epilogue: bias (from smem) + store, zero acc
        const int g = lane >> 2;
        const float* bs = reinterpret_cast<const float*>(smem + OFF_BIAS);
#pragma unroll
        for (int t = 0; t < 2; t++) {
            float* r0 = out + (size_t)(m0 + t * 16 + g) * FDIM;
            float* r1 = r0 + 8 * FDIM;
#pragma unroll
            for (int j = 0; j < 8; j++) {
                int col = 8 * j + 2 * tig;
                float2 bv = *reinterpret_cast<const float2*>(bs + col);
                float2 o0 = { acc[0 + t][j][0] + bv.x, acc[t][j][1] + bv.y };
                float2 o1 = { acc[t][j][2] + bv.x, acc[t][j][3] + bv.y };
                *reinterpret_cast<float2*>(r0 + col) = o0;
                *reinterpret_cast<float2*>(r1 + col) = o1;
                acc[t][j][0] = 0.f; acc[t][j][1] = 0.f;
                acc[t][j][2] = 0.f; acc[t][j][3] = 0.f;
            }
        }
    }
}

extern "C" void kernel_launch(void* const* d_in, const int* in_sizes, int n_in,
                              void* d_out, int out_size)
{
    const float* x    = (const float*)d_in[0];   // (B, N, 64) fp32
    const int*   adjc = (const int*)d_in[1];     // (N, 9) int32
    const float* W    = (const float*)d_in[2];   // (9, 64, 64) fp32
    const float* bias = (const float*)d_in[3];   // (64,) fp32
    float*       out  = (float*)d_out;

    const int Nn = in_sizes[1] / KNBR;
    const long long M = (long long)out_size / FDIM;
    const int nwt = (int)(M / MW);               // 12288 warp-tiles

    cudaFuncSetAttribute(nhconv_ws, cudaFuncAttributeMaxDynamicSharedMemorySize, SMEM_TOTAL);

    int nsm = 148;
    cudaDeviceGetAttribute(&nsm, cudaDevAttrMultiProcessorCount, 0);

    prep_W<<<(KNBR * FDIM * FDIM + 255) / 256, 256>>>(W);
    nhconv_ws<<<nsm, NTHREADS, SMEM_TOTAL>>>(x, adjc, bias, out, Nn, nwt);
}